// round 11
// baseline (speedup 1.0000x reference)
#include <cuda_runtime.h>
#include <cuda_fp16.h>
#include <cstdint>

// GroupedHybridFFN: B=4,S=4096,D=2048; E=8 experts of d=256; H=1024
//   e 0..1: KAN (lin -> tanh -> Chebyshev; T0 folded to bias, T3 derived in smem)
//   e 2..7: MLP (w1 -> gelu(tanh) -> w2)
// R11: 2 CTAs/SM x 128 threads (independent barrier domains), M=64/CTA,
//      H-chunks of 64, all loads prefetch-covered, regs 255 no spill.

#define TILE_HALFS 32768          // 64KB stored fp16 weight tile

#define NTHREADS  128
#define SMEM_MAIN 114688          // 112KB per CTA, 2 CTAs/SM

// MLP smem layout (bytes)
#define MB1   0                   // 1024 halfs b1
#define MX    2048                // 32KB X [64,256] RS512
#define MWA   34816               // 32KB W1 chunk [64,256] RS512
#define MWB   67584               // 32KB W2 k-half [256,64] RS128
#define MACT  100352              // 8KB act [64,64] RS128
// KAN smem layout
#define KX    0                   // 32KB X
#define KW    32768               // 32KB W1k chunk [64,256] RS512
#define KPA   65536               // 16KB poly pass [128,64] RS128
#define KPB   81920               // 16KB
#define KT0   98304               // 8KB t tile [64,64] RS128
#define KT1   106496              // 8KB T2 (later T3) tile

static __device__ __align__(128) __half g_B1 [64u * TILE_HALFS];  // [e8][c8]  N128,K256 RS512
static __device__ __align__(128) __half g_B2m[48u * TILE_HALFS];  // [e6][c8]  N256,K128 RS256
static __device__ __align__(128) __half g_B2k[48u * TILE_HALFS];  // [(e*8+c)*3+p] N256,K128 RS256
static __device__ float g_c0[512];

// ---------------- helpers ----------------
__device__ __forceinline__ uint32_t smem_u32(const void* p){
    uint32_t a;
    asm("{ .reg .u64 t; cvta.to.shared.u64 t, %1; cvt.u32.u64 %0, t; }" : "=r"(a) : "l"(p));
    return a;
}
__device__ __forceinline__ void cpa16(uint32_t dst, const void* src){
    asm volatile("cp.async.cg.shared.global [%0], [%1], 16;" :: "r"(dst), "l"(src) : "memory");
}
__device__ __forceinline__ void cp_commit(){ asm volatile("cp.async.commit_group;" ::: "memory"); }
__device__ __forceinline__ void cp_wait0(){ asm volatile("cp.async.wait_group 0;" ::: "memory"); }

__device__ __forceinline__ void ldmx4(uint32_t (&r)[4], uint32_t addr){
    asm volatile("ldmatrix.sync.aligned.m8n8.x4.shared.b16 {%0,%1,%2,%3}, [%4];"
        : "=r"(r[0]), "=r"(r[1]), "=r"(r[2]), "=r"(r[3]) : "r"(addr));
}
__device__ __forceinline__ void mma16816(float (&d)[4], const uint32_t (&a)[4],
                                         uint32_t b0, uint32_t b1){
    asm volatile("mma.sync.aligned.m16n8k16.row.col.f32.f16.f16.f32 "
        "{%0,%1,%2,%3},{%4,%5,%6,%7},{%8,%9},{%0,%1,%2,%3};"
        : "+f"(d[0]), "+f"(d[1]), "+f"(d[2]), "+f"(d[3])
        : "r"(a[0]), "r"(a[1]), "r"(a[2]), "r"(a[3]), "r"(b0), "r"(b1));
}
__device__ __forceinline__ float tanh_fast(float y){
    float e = __expf(2.0f * y);
    return 1.0f - __fdividef(2.0f, e + 1.0f);
}
__device__ __forceinline__ float gelu_tanh(float v){
    float inner = 0.7978845608028654f * fmaf(0.044715f * v * v, v, v);
    return 0.5f * v * (1.0f + tanh_fast(inner));
}
// contiguous NB-byte stream into smem + commit
template<int NB>
__device__ __forceinline__ void pf_tile(uint32_t sdst, const __half* src, int tid){
#pragma unroll
    for (int i = 0; i < NB / (NTHREADS * 16); i++)
        cpa16(sdst + (uint32_t)(i * NTHREADS + tid) * 16, src + (size_t)(i * NTHREADS + tid) * 8);
    cp_commit();
}
// k-half of an RS256 [256,128] tile -> RS128 [256,64] (32KB)
__device__ __forceinline__ void pf_khalf256(uint32_t sdst, const __half* src, int hh, int tid){
#pragma unroll
    for (int i = 0; i < 16; i++){
        int idx = i * NTHREADS + tid;            // 2048 granules of 16B
        uint32_t n = (uint32_t)idx >> 3, g = ((uint32_t)idx & 7u) * 16;
        cpa16(sdst + n * 128 + g, src + (size_t)n * 128 + (size_t)hh * 64 + g / 2);
    }
    cp_commit();
}
// (oh,hh) sub-tile of an RS256 [256,128] tile -> RS128 [128,64] (16KB)
__device__ __forceinline__ void pf_sub(uint32_t sdst, const __half* src, int oh, int hh, int tid){
#pragma unroll
    for (int i = 0; i < 8; i++){
        int idx = i * NTHREADS + tid;            // 1024 granules of 16B
        uint32_t n = (uint32_t)idx >> 3, g = ((uint32_t)idx & 7u) * 16;
        cpa16(sdst + n * 128 + g,
              src + (size_t)(oh * 128 + n) * 128 + (size_t)hh * 64 + g / 2);
    }
    cp_commit();
}

// ---------------- prep: fp32 weights -> fp16 swizzled [N,K] tiles (+ c0 sums) ------
__global__ void __launch_bounds__(256) prep_tiles(
    const float* __restrict__ kan_lin_w, const float* __restrict__ mlp_w1,
    const float* __restrict__ mlp_w2,    const float* __restrict__ kan_poly_w)
{
    extern __shared__ __half sh[];
    int bid = blockIdx.x, tid = threadIdx.x;

    if (bid >= 160){                        // c0: colsum of kan poly W0 (experts 0,1)
        int e = bid - 160;
        const float* p0 = kan_poly_w + (size_t)e * 4 * 1024 * 256;
        float s = 0.f;
        for (int h = 0; h < 1024; h++) s += p0[(size_t)h * 256 + tid];
        g_c0[e * 256 + tid] = s;
        return;
    }

    const float* src; __half* dst;
    uint32_t N, RS, sstr;

    if (bid < 64){                         // B1: B[n,k] = W1[k][c*128+n]
        int e = bid >> 3, c = bid & 7;
        src = (e < 2 ? kan_lin_w + (size_t)e * 256 * 1024
                     : mlp_w1   + (size_t)(e - 2) * 256 * 1024) + c * 128;
        N = 128; RS = 512; sstr = 1024; dst = g_B1 + (size_t)bid * TILE_HALFS;
    } else if (bid < 112){                 // B2m: B[n,k] = W2[c*128+k][n]
        int i = bid - 64; int e = i >> 3, c = i & 7;
        src = mlp_w2 + (size_t)e * 1024 * 256 + (size_t)c * 128 * 256;
        N = 256; RS = 256; sstr = 256; dst = g_B2m + (size_t)i * TILE_HALFS;
    } else {                               // B2k: poly p=1..3
        int i = bid - 112; int e = i / 24; int r = i % 24; int c = r / 3; int p = r % 3;
        src = kan_poly_w + (size_t)e * 4 * 1024 * 256 + (size_t)(p + 1) * 1024 * 256
            + (size_t)c * 128 * 256;
        N = 256; RS = 256; sstr = 256; dst = g_B2k + (size_t)i * TILE_HALFS;
    }
    for (uint32_t idx = tid; idx < TILE_HALFS; idx += 256){
        uint32_t n = idx & (N - 1), k = idx / N;
        uint32_t off = n * RS + ((k * 2) ^ ((n & 7u) << 4));
        sh[off >> 1] = __float2half_rn(src[(size_t)k * sstr + n]);
    }
    __syncthreads();
    const uint4* s4 = (const uint4*)sh;
    uint4* d4 = (uint4*)dst;
    for (uint32_t t = tid; t < TILE_HALFS / 8; t += 256) d4[t] = s4[t];
}

// ---------------- main fused kernel: 2048 CTAs, 128 threads (4 warps) --------------
__global__ void __launch_bounds__(NTHREADS, 2) ffn_main(
    const float* __restrict__ x,      const float* __restrict__ kan_bias,
    const float* __restrict__ mlp_b1, const float* __restrict__ mlp_b2,
    float* __restrict__ out)
{
    extern __shared__ char smem[];
    uint32_t sb = smem_u32(smem);

    int tid = threadIdx.x, wid = tid >> 5, lane = tid & 31;
    int bx = blockIdx.x;
    int e = bx >> 8, tile = bx & 255;          // KAN experts (e<2) first
    int row0 = tile * 64;
    bool is_kan = (e < 2);

    // stage1 grid: 2m x 2n -> warp tile m32 x n32 over [64,64]
    int m1 = (wid >> 1) * 32, n1 = (wid & 1) * 32;

    uint32_t lrow = lane & 15;
    uint32_t lkhi = (uint32_t)(lane >> 4) << 4;
    uint32_t axor = (lrow & 7u) << 4;
    uint32_t xr = ((uint32_t)(lane >> 2) & 7u) << 4;

    const uint32_t sX = sb + (is_kan ? KX : MX);
    const uint32_t sW1 = sb + (is_kan ? KW : MWA);

    // ---- prefetch W1 chunk 0 (rows 0..63 of the c=0 tile) ----
    pf_tile<32768>(sW1, g_B1 + ((size_t)(e * 8) << 15), tid);

    // ---- X tile [64,256] fp32 -> fp16 swizzled (512B rows) ----
    const float* xp = x + (size_t)row0 * 2048 + e * 256;
#pragma unroll
    for (int it = 0; it < 32; it++){
        int idx = it * NTHREADS + tid;
        int r = idx >> 6, q = idx & 63;
        float4 v = *(const float4*)(xp + (size_t)r * 2048 + q * 4);
        uint32_t off = (uint32_t)r * 512 + (((uint32_t)q * 8) ^ ((r & 7u) << 4));
        half2 h0 = __floats2half2_rn(v.x, v.y);
        half2 h1 = __floats2half2_rn(v.z, v.w);
        *(uint2*)(smem + (is_kan ? KX : MX) + off) = make_uint2(*(uint32_t*)&h0, *(uint32_t*)&h1);
    }
    if (!is_kan){
        const float* b1p = mlp_b1 + (size_t)(e - 2) * 1024;
        for (int i = tid; i < 1024; i += NTHREADS)
            ((__half*)(smem + MB1))[i] = __float2half_rn(b1p[i]);
    }

    // ---- output accumulators: [64,256] over 4 warps ----
    // MLP: warp tile m64 x o64 (o2 = wid*64), blk: oc = wid*64 + blk*8
    // KAN: warp m64 x o32 per half, blk: oc = (blk>>2)*128 + wid*32 + (blk&3)*8
    float acc2[4][8][4];
#pragma unroll
    for (int mt = 0; mt < 4; mt++)
#pragma unroll
        for (int ot = 0; ot < 8; ot++)
#pragma unroll
            for (int i = 0; i < 4; i++) acc2[mt][ot][i] = 0.f;

    for (int cc = 0; cc < 16; cc++){
        int c = cc >> 1, hh = cc & 1;

        cp_wait0(); __syncthreads();           // W1(cc) ready; stage-2 buffers free
        if (is_kan)
            pf_sub(sb + KPA, g_B2k + ((size_t)((e * 8 + c) * 3) << 15), 0, hh, tid);
        else
            pf_khalf256(sb + MWB, g_B2m + ((size_t)((e - 2) * 8 + c) << 15), hh, tid);

        // ---------- stage 1: [64,64] = X[64,256] @ W1cc[64,256]^T ----------
        float acc1[2][4][4];
#pragma unroll
        for (int mt = 0; mt < 2; mt++)
#pragma unroll
            for (int nt = 0; nt < 4; nt++)
#pragma unroll
                for (int i = 0; i < 4; i++) acc1[mt][nt][i] = 0.f;
#pragma unroll
        for (int ks = 0; ks < 16; ks++){
            uint32_t kx = ((uint32_t)ks * 32 + lkhi) ^ axor;
            uint32_t a[2][4], b[2][4];
            ldmx4(a[0], sX  + (uint32_t)(m1 + lrow) * 512      + kx);
            ldmx4(a[1], sX  + (uint32_t)(m1 + 16 + lrow) * 512 + kx);
            ldmx4(b[0], sW1 + (uint32_t)(n1 + lrow) * 512      + kx);
            ldmx4(b[1], sW1 + (uint32_t)(n1 + 16 + lrow) * 512 + kx);
#pragma unroll
            for (int mt = 0; mt < 2; mt++)
#pragma unroll
                for (int j = 0; j < 2; j++){
                    mma16816(acc1[mt][j * 2],     a[mt], b[j][0], b[j][2]);
                    mma16816(acc1[mt][j * 2 + 1], a[mt], b[j][1], b[j][3]);
                }
        }

        // ---------- epilogue 1 ----------
        if (is_kan){
#pragma unroll
            for (int mt = 0; mt < 2; mt++)
#pragma unroll
            for (int nt = 0; nt < 4; nt++){
                float* d = acc1[mt][nt];
                int r0 = m1 + mt * 16 + (lane >> 2);
                int ncol = n1 + nt * 8 + (lane & 3) * 2;
                uint32_t cb = ((uint32_t)ncol * 2) ^ xr;
#pragma unroll
                for (int h = 0; h < 2; h++){
                    float t0 = tanh_fast(d[h * 2]);
                    float t1 = tanh_fast(d[h * 2 + 1]);
                    float u0 = fmaf(2.f * t0, t0, -1.f);
                    float u1 = fmaf(2.f * t1, t1, -1.f);
                    uint32_t ro = (uint32_t)(r0 + h * 8) * 128 + cb;
                    *(half2*)(smem + KT0 + ro) = __floats2half2_rn(t0, t1);
                    *(half2*)(smem + KT1 + ro) = __floats2half2_rn(u0, u1);
                }
            }
        } else {
            const __half* b1h = (const __half*)(smem + MB1) + cc * 64;
#pragma unroll
            for (int mt = 0; mt < 2; mt++)
#pragma unroll
            for (int nt = 0; nt < 4; nt++){
                float* d = acc1[mt][nt];
                int r0 = m1 + mt * 16 + (lane >> 2);
                int ncol = n1 + nt * 8 + (lane & 3) * 2;
                half2 bh = *(const half2*)(b1h + ncol);
                float bb0 = __half2float(__low2half(bh));
                float bb1 = __half2float(__high2half(bh));
                uint32_t cb = ((uint32_t)ncol * 2) ^ xr;
#pragma unroll
                for (int h = 0; h < 2; h++){
                    float g0 = gelu_tanh(d[h * 2]     + bb0);
                    float g1 = gelu_tanh(d[h * 2 + 1] + bb1);
                    *(half2*)(smem + MACT + (uint32_t)(r0 + h * 8) * 128 + cb)
                        = __floats2half2_rn(g0, g1);
                }
            }
        }

        // ---------- stage 2 ----------
        if (!is_kan){
            cp_wait0(); __syncthreads();       // W2 half ready; act visible; WA free
            if (cc < 15)
                pf_tile<32768>(sW1, g_B1 + (((size_t)(e * 8 + ((cc + 1) >> 1)) << 15)
                                            + ((size_t)((cc + 1) & 1) << 14)), tid);
            // acc2 += act[64,64] @ W2h[256,64]^T  (warp m64 x o64)
#pragma unroll
            for (int ks = 0; ks < 4; ks++){
                uint32_t kx = ((uint32_t)ks * 32 + lkhi) ^ axor;
                uint32_t a[4][4], b[4][4];
#pragma unroll
                for (int mt = 0; mt < 4; mt++)
                    ldmx4(a[mt], sb + MACT + (uint32_t)(mt * 16 + lrow) * 128 + kx);
#pragma unroll
                for (int ot = 0; ot < 4; ot++)
                    ldmx4(b[ot], sb + MWB + (uint32_t)(wid * 64 + ot * 16 + lrow) * 128 + kx);
#pragma unroll
                for (int mt = 0; mt < 4; mt++)
#pragma unroll
                    for (int ot = 0; ot < 4; ot++){
                        mma16816(acc2[mt][ot * 2],     a[mt], b[ot][0], b[ot][2]);
                        mma16816(acc2[mt][ot * 2 + 1], a[mt], b[ot][1], b[ot][3]);
                    }
            }
        } else {
            const __half* poly = g_B2k + ((size_t)((e * 8 + c) * 3) << 15);
            // 6 passes: (p,oh) with act sel; T3 derived in smem after T2 passes
            uint32_t bufs[2] = { sb + KPA, sb + KPB };
            int cur = 0;
#pragma unroll 1
            for (int pass = 0; pass < 6; pass++){
                int p = pass >> 1, oh = pass & 1;
                cp_wait0(); __syncthreads();   // bufs[cur] = pass data ready (+acts on pass0)
                if (pass == 3){
                    // transform KT1: T2 -> T3 = 2*t*T2 - t (after both T2 passes read it)
                    // (pass 3 wait/sync above also guarantees pass-2 g2 completed)
                }
                // prefetch next
                if (pass < 5){
                    int np = (pass + 1) >> 1, noh = (pass + 1) & 1;
                    pf_sub(bufs[cur ^ 1], poly + (size_t)np * TILE_HALFS, noh, hh, tid);
                } else {
                    pf_tile<32768>(sW1, g_B1 + (((size_t)(e * 8 + ((cc + 1) >> 1)) << 15)
                                                + ((size_t)(((cc + 1) & 15) & 1) << 14)), tid);
                }
                // act select: p0 -> t (KT0), p1 -> T2 (KT1), p2 -> T3 (KT1 transformed)
                uint32_t sA = (p == 0) ? (sb + KT0) : (sb + KT1);
                if (pass == 4){
                    // before first T3 pass: transform must have happened — do it at pass 4
                    // (pass-4's wait/sync above guarantees pass-3 (last T2 read) is done)
                    for (int i = tid; i < 2048; i += NTHREADS){
                        half2 tv = ((half2*)(smem + KT0))[i];
                        half2 uv = ((half2*)(smem + KT1))[i];
                        float t0 = __half2float(__low2half(tv)),  t1 = __half2float(__high2half(tv));
                        float u0 = __half2float(__low2half(uv)),  u1 = __half2float(__high2half(uv));
                        ((half2*)(smem + KT1))[i] =
                            __floats2half2_rn(fmaf(2.f * t0, u0, -t0), fmaf(2.f * t1, u1, -t1));
                    }
                    __syncthreads();
                }
                // acc2 += act[64,64] @ polyhalf[128,64]^T (warp m64 x o32, half oh)
#pragma unroll
                for (int ks = 0; ks < 4; ks++){
                    uint32_t kx = ((uint32_t)ks * 32 + lkhi) ^ axor;
                    uint32_t a[4][4], b[2][4];
#pragma unroll
                    for (int mt = 0; mt < 4; mt++)
                        ldmx4(a[mt], sA + (uint32_t)(mt * 16 + lrow) * 128 + kx);
#pragma unroll
                    for (int j = 0; j < 2; j++)
                        ldmx4(b[j], bufs[cur] + (uint32_t)(wid * 32 + j * 16 + lrow) * 128 + kx);
#pragma unroll
                    for (int mt = 0; mt < 4; mt++)
#pragma unroll
                        for (int j = 0; j < 2; j++){
                            mma16816(acc2[mt][oh * 4 + j * 2],     a[mt], b[j][0], b[j][2]);
                            mma16816(acc2[mt][oh * 4 + j * 2 + 1], a[mt], b[j][1], b[j][3]);
                        }
                }
                cur ^= 1;
            }
        }
    }

    // ---------- final store: acc2 + bias -> gmem fp32 ----------
#pragma unroll
    for (int mt = 0; mt < 4; mt++)
#pragma unroll
    for (int blk = 0; blk < 8; blk++){
        float* d = acc2[mt][blk];
        int oc = is_kan ? ((blk >> 2) * 128 + wid * 32 + (blk & 3) * 8 + (lane & 3) * 2)
                        : (wid * 64 + blk * 8 + (lane & 3) * 2);
        float bb0, bb1;
        if (is_kan){
            bb0 = __ldg(kan_bias + e * 256 + oc)     + g_c0[e * 256 + oc];
            bb1 = __ldg(kan_bias + e * 256 + oc + 1) + g_c0[e * 256 + oc + 1];
        } else {
            bb0 = __ldg(mlp_b2 + (e - 2) * 256 + oc);
            bb1 = __ldg(mlp_b2 + (e - 2) * 256 + oc + 1);
        }
        int r0 = row0 + mt * 16 + (lane >> 2);
        float* op0 = out + (size_t)r0 * 2048 + e * 256 + oc;
        float* op1 = op0 + 8 * 2048;
        op0[0] = d[0] + bb0;  op0[1] = d[1] + bb1;
        op1[0] = d[2] + bb0;  op1[1] = d[3] + bb1;
    }
}

// ---------------- kernel_launch ----------------
extern "C" void kernel_launch(void* const* d_in, const int* in_sizes, int n_in,
                              void* d_out, int out_size)
{
    const float* x   = (const float*)d_in[0];
    const float* klw = (const float*)d_in[1];
    const float* kpw = (const float*)d_in[2];
    const float* kb  = (const float*)d_in[3];
    const float* w1  = (const float*)d_in[4];
    const float* b1  = (const float*)d_in[5];
    const float* w2  = (const float*)d_in[6];
    const float* b2  = (const float*)d_in[7];
    float* out = (float*)d_out;
    (void)in_sizes; (void)n_in; (void)out_size;

    cudaFuncSetAttribute(prep_tiles, cudaFuncAttributeMaxDynamicSharedMemorySize, 65536);
    cudaFuncSetAttribute(ffn_main,   cudaFuncAttributeMaxDynamicSharedMemorySize, SMEM_MAIN);

    prep_tiles<<<162, 256, 65536>>>(klw, w1, w2, kpw);
    ffn_main<<<2048, NTHREADS, SMEM_MAIN>>>(x, kb, b1, b2, out);
}

// round 12
// speedup vs baseline: 2.3558x; 2.3558x over previous
#include <cuda_runtime.h>
#include <cuda_fp16.h>
#include <cstdint>

// GroupedHybridFFN: B=4,S=4096,D=2048; E=8 experts of d=256; H=1024
//   e 0..1: KAN (lin -> tanh -> Chebyshev T1..T3 -> poly proj; T0 folded to bias)
//   e 2..7: MLP (w1 -> gelu(tanh) -> w2)
// R12: R10 structure + explicit fragment double-buffering in all MMA k-loops
//      (break ldmatrix->mma serialization; tensor pipe was pinned at 47%).

#define TILE_HALFS 32768          // 64KB fp16 weight tile

// smem layout (bytes) — MLP view
#define OFF_B1H   0               // 1024 halfs (mlp b1, whole expert)
#define OFF_X     2048            // 64KB  X tile [128,256] swizzled (512B rows)
#define OFF_WA    67584           // 64KB  weight buffer A (W1 chunk)
#define OFF_WB    133120          // 64KB  weight buffer B (W2 chunk)
#define OFF_ACT   198656          // 32KB  act tile [128,128] (256B rows)
// KAN view (same block): KWA/KWB 32KB each, 3 act tiles 16KB each
#define OFF_KWA   67584
#define OFF_KWB   100352
#define OFF_KT    133120          // 3 x 16KB [128,64] (128B rows)
#define SMEM_MAIN 231424

#define NTHREADS  256

static __device__ __align__(128) __half g_B1 [64u * TILE_HALFS];  // [e8][c8]  N128,K256 RS512
static __device__ __align__(128) __half g_B2m[48u * TILE_HALFS];  // [e6][c8]  N256,K128 RS256
static __device__ __align__(128) __half g_B2k[48u * TILE_HALFS];  // [(e*8+c)*3+p] N256,K128 RS256
static __device__ float g_c0[512];

// ---------------- helpers ----------------
__device__ __forceinline__ uint32_t smem_u32(const void* p){
    uint32_t a;
    asm("{ .reg .u64 t; cvta.to.shared.u64 t, %1; cvt.u32.u64 %0, t; }" : "=r"(a) : "l"(p));
    return a;
}
__device__ __forceinline__ void cpa16(uint32_t dst, const void* src){
    asm volatile("cp.async.cg.shared.global [%0], [%1], 16;" :: "r"(dst), "l"(src) : "memory");
}
__device__ __forceinline__ void cp_commit(){ asm volatile("cp.async.commit_group;" ::: "memory"); }
__device__ __forceinline__ void cp_wait0(){ asm volatile("cp.async.wait_group 0;" ::: "memory"); }

__device__ __forceinline__ void ldmx4(uint32_t (&r)[4], uint32_t addr){
    asm volatile("ldmatrix.sync.aligned.m8n8.x4.shared.b16 {%0,%1,%2,%3}, [%4];"
        : "=r"(r[0]), "=r"(r[1]), "=r"(r[2]), "=r"(r[3]) : "r"(addr));
}
__device__ __forceinline__ void mma16816(float (&d)[4], const uint32_t (&a)[4],
                                         uint32_t b0, uint32_t b1){
    asm volatile("mma.sync.aligned.m16n8k16.row.col.f32.f16.f16.f32 "
        "{%0,%1,%2,%3},{%4,%5,%6,%7},{%8,%9},{%0,%1,%2,%3};"
        : "+f"(d[0]), "+f"(d[1]), "+f"(d[2]), "+f"(d[3])
        : "r"(a[0]), "r"(a[1]), "r"(a[2]), "r"(a[3]), "r"(b0), "r"(b1));
}
__device__ __forceinline__ float tanh_fast(float y){
    float e = __expf(2.0f * y);
    return 1.0f - __fdividef(2.0f, e + 1.0f);
}
__device__ __forceinline__ float gelu_tanh(float v){
    float inner = 0.7978845608028654f * fmaf(0.044715f * v * v, v, v);
    return 0.5f * v * (1.0f + tanh_fast(inner));
}
// contiguous NB-byte stream into smem + commit (256 threads)
template<int NB>
__device__ __forceinline__ void pf_tile(uint32_t sdst, const __half* src, int tid){
#pragma unroll
    for (int i = 0; i < NB / (NTHREADS * 16); i++)
        cpa16(sdst + (uint32_t)(i * NTHREADS + tid) * 16, src + (size_t)(i * NTHREADS + tid) * 8);
    cp_commit();
}
// KAN poly k-half sub-tile: src [256,128] RS256 -> dst [256,64] RS128 (half h)
__device__ __forceinline__ void pf_poly_half(uint32_t sdst, const __half* src, int h, int tid){
#pragma unroll
    for (int i = 0; i < 8; i++){
        int idx = i * NTHREADS + tid;            // 2048 granules of 16B
        uint32_t n = (uint32_t)idx >> 3, g = ((uint32_t)idx & 7u) * 16;
        cpa16(sdst + n * 128 + g, src + (size_t)n * 128 + (size_t)h * 64 + g / 2);
    }
    cp_commit();
}

// ---------------- prep: fp32 weights -> fp16 swizzled [N,K] tiles (+ c0 sums) ------
// layout: byte_off(n,k) = n*(2K) + ((2k) ^ ((n&7)<<4))
__global__ void __launch_bounds__(256) prep_tiles(
    const float* __restrict__ kan_lin_w, const float* __restrict__ mlp_w1,
    const float* __restrict__ mlp_w2,    const float* __restrict__ kan_poly_w)
{
    extern __shared__ __half sh[];
    int bid = blockIdx.x, tid = threadIdx.x;

    if (bid >= 160){                        // c0: colsum of kan poly W0 (experts 0,1)
        int e = bid - 160;
        const float* p0 = kan_poly_w + (size_t)e * 4 * 1024 * 256;
        float s = 0.f;
        for (int h = 0; h < 1024; h++) s += p0[(size_t)h * 256 + tid];
        g_c0[e * 256 + tid] = s;
        return;
    }

    const float* src; __half* dst;
    uint32_t N, RS, sstr;

    if (bid < 64){                         // B1: B[n,k] = W1[k][c*128+n]
        int e = bid >> 3, c = bid & 7;
        src = (e < 2 ? kan_lin_w + (size_t)e * 256 * 1024
                     : mlp_w1   + (size_t)(e - 2) * 256 * 1024) + c * 128;
        N = 128; RS = 512; sstr = 1024; dst = g_B1 + (size_t)bid * TILE_HALFS;
    } else if (bid < 112){                 // B2m: B[n,k] = W2[c*128+k][n]
        int i = bid - 64; int e = i >> 3, c = i & 7;
        src = mlp_w2 + (size_t)e * 1024 * 256 + (size_t)c * 128 * 256;
        N = 256; RS = 256; sstr = 256; dst = g_B2m + (size_t)i * TILE_HALFS;
    } else {                               // B2k: poly p=1..3
        int i = bid - 112; int e = i / 24; int r = i % 24; int c = r / 3; int p = r % 3;
        src = kan_poly_w + (size_t)e * 4 * 1024 * 256 + (size_t)(p + 1) * 1024 * 256
            + (size_t)c * 128 * 256;
        N = 256; RS = 256; sstr = 256; dst = g_B2k + (size_t)i * TILE_HALFS;
    }
    for (uint32_t idx = tid; idx < TILE_HALFS; idx += 256){
        uint32_t n = idx & (N - 1), k = idx / N;
        uint32_t off = n * RS + ((k * 2) ^ ((n & 7u) << 4));
        sh[off >> 1] = __float2half_rn(src[(size_t)k * sstr + n]);
    }
    __syncthreads();
    const uint4* s4 = (const uint4*)sh;
    uint4* d4 = (uint4*)dst;
    for (uint32_t t = tid; t < TILE_HALFS / 8; t += 256) d4[t] = s4[t];
}

// ---------------- stage-2 GEMM (pipelined): acc2 += A[128,KS*16] @ B[256,KS*16]^T --
// 8-warp grid 2m x 4o -> warp tile m64 x o64. RS = row stride bytes of both tiles.
template<int KS, int RS>
__device__ __forceinline__ void gemm2_pass(
    float (&acc2)[4][8][4], uint32_t sA, uint32_t sB,
    int m2, int o2, uint32_t lrow, uint32_t lkhi, uint32_t axor)
{
    uint32_t a[2][4][4], b[2][4][4];
    // prologue: load k-step 0
    {
        uint32_t kx = lkhi ^ axor;
#pragma unroll
        for (int mt = 0; mt < 4; mt++)
            ldmx4(a[0][mt], sA + (uint32_t)(m2 + mt * 16 + lrow) * RS + kx);
#pragma unroll
        for (int ot = 0; ot < 4; ot++)
            ldmx4(b[0][ot], sB + (uint32_t)(o2 + ot * 16 + lrow) * RS + kx);
    }
#pragma unroll
    for (int ks = 0; ks < KS; ks++){
        int cur = ks & 1, nxt = cur ^ 1;
        if (ks + 1 < KS){
            uint32_t kx = ((uint32_t)(ks + 1) * 32 + lkhi) ^ axor;
#pragma unroll
            for (int mt = 0; mt < 4; mt++)
                ldmx4(a[nxt][mt], sA + (uint32_t)(m2 + mt * 16 + lrow) * RS + kx);
#pragma unroll
            for (int ot = 0; ot < 4; ot++)
                ldmx4(b[nxt][ot], sB + (uint32_t)(o2 + ot * 16 + lrow) * RS + kx);
        }
#pragma unroll
        for (int mt = 0; mt < 4; mt++)
#pragma unroll
            for (int ot = 0; ot < 4; ot++){
                mma16816(acc2[mt][ot * 2],     a[cur][mt], b[cur][ot][0], b[cur][ot][2]);
                mma16816(acc2[mt][ot * 2 + 1], a[cur][mt], b[cur][ot][1], b[cur][ot][3]);
            }
    }
}

// ---------------- stage-1 GEMM (pipelined): acc1 += X[m32,256] @ W[n32,256]^T ------
__device__ __forceinline__ void gemm1_pass(
    float (&acc1)[2][4][4], uint32_t sX, uint32_t sW,
    int m1, int n0, uint32_t lrow, uint32_t lkhi, uint32_t axor)
{
    uint32_t a[2][2][4], b[2][2][4];
    {
        uint32_t kx = lkhi ^ axor;
        ldmx4(a[0][0], sX + (uint32_t)(m1 + lrow) * 512      + kx);
        ldmx4(a[0][1], sX + (uint32_t)(m1 + 16 + lrow) * 512 + kx);
        ldmx4(b[0][0], sW + (uint32_t)(n0 + lrow) * 512      + kx);
        ldmx4(b[0][1], sW + (uint32_t)(n0 + 16 + lrow) * 512 + kx);
    }
#pragma unroll
    for (int ks = 0; ks < 16; ks++){
        int cur = ks & 1, nxt = cur ^ 1;
        if (ks < 15){
            uint32_t kx = ((uint32_t)(ks + 1) * 32 + lkhi) ^ axor;
            ldmx4(a[nxt][0], sX + (uint32_t)(m1 + lrow) * 512      + kx);
            ldmx4(a[nxt][1], sX + (uint32_t)(m1 + 16 + lrow) * 512 + kx);
            ldmx4(b[nxt][0], sW + (uint32_t)(n0 + lrow) * 512      + kx);
            ldmx4(b[nxt][1], sW + (uint32_t)(n0 + 16 + lrow) * 512 + kx);
        }
#pragma unroll
        for (int mt = 0; mt < 2; mt++)
#pragma unroll
            for (int j = 0; j < 2; j++){
                mma16816(acc1[mt][j * 2],     a[cur][mt], b[cur][j][0], b[cur][j][2]);
                mma16816(acc1[mt][j * 2 + 1], a[cur][mt], b[cur][j][1], b[cur][j][3]);
            }
    }
}

// ---------------- main fused kernel: 1024 CTAs, 256 threads (8 warps) --------------
__global__ void __launch_bounds__(NTHREADS, 1) ffn_main(
    const float* __restrict__ x,      const float* __restrict__ kan_bias,
    const float* __restrict__ mlp_b1, const float* __restrict__ mlp_b2,
    float* __restrict__ out)
{
    extern __shared__ char smem[];
    uint32_t sb = smem_u32(smem);
    const uint32_t sX = sb + OFF_X;

    int tid = threadIdx.x, wid = tid >> 5, lane = tid & 31;
    int bx = blockIdx.x;
    int e = bx >> 7, tile = bx & 127;          // KAN experts (e<2) first
    int row0 = tile * 128;
    bool is_kan = (e < 2);

    // stage1 grid: 4m x 2n -> warp tile m32 x n{64 mlp (two n32 passes) | 32 kan}
    int m1 = (wid >> 1) * 32, nhalf = wid & 1;
    // stage2 grid: 2m x 4o -> warp tile m64 x o64
    int m2 = (wid >> 2) * 64, o2 = (wid & 3) * 64;

    uint32_t lrow = lane & 15;
    uint32_t lkhi = (uint32_t)(lane >> 4) << 4;
    uint32_t axor = (lrow & 7u) << 4;
    uint32_t xr = ((uint32_t)(lane >> 2) & 7u) << 4;

    // ---- first weight prefetch (overlaps X load) ----
    if (is_kan) pf_tile<32768>(sb + OFF_KWA, g_B1 + ((size_t)(e * 8) << 15), tid);
    else        pf_tile<65536>(sb + OFF_WA,  g_B1 + ((size_t)(e * 8) << 15), tid);

    // ---- X tile [128,256] fp32 -> fp16 swizzled (512B rows) ----
    const float* xp = x + (size_t)row0 * 2048 + e * 256;
#pragma unroll
    for (int it = 0; it < 32; it++){
        int idx = it * NTHREADS + tid;
        int r = idx >> 6, q = idx & 63;
        float4 v = *(const float4*)(xp + (size_t)r * 2048 + q * 4);
        uint32_t off = (uint32_t)r * 512 + (((uint32_t)q * 8) ^ ((r & 7u) << 4));
        half2 h0 = __floats2half2_rn(v.x, v.y);
        half2 h1 = __floats2half2_rn(v.z, v.w);
        *(uint2*)(smem + OFF_X + off) = make_uint2(*(uint32_t*)&h0, *(uint32_t*)&h1);
    }
    if (!is_kan){
        const float* b1p = mlp_b1 + (size_t)(e - 2) * 1024;
        for (int i = tid; i < 1024; i += NTHREADS)
            ((__half*)(smem + OFF_B1H))[i] = __float2half_rn(b1p[i]);
    }

    // ---- output accumulators: m64 x o64 per warp (128 regs) ----
    float acc2[4][8][4];
#pragma unroll
    for (int mt = 0; mt < 4; mt++)
#pragma unroll
        for (int ot = 0; ot < 8; ot++)
#pragma unroll
            for (int i = 0; i < 4; i++) acc2[mt][ot][i] = 0.f;

    if (!is_kan){
        // =========================== MLP path (chunks of 128 H) ===========================
        const uint32_t sWA = sb + OFF_WA, sWB = sb + OFF_WB, sACT = sb + OFF_ACT;
        for (int c = 0; c < 8; c++){
            cp_wait0(); __syncthreads();               // W1(c) ready; WB free
            pf_tile<65536>(sWB, g_B2m + ((size_t)((e - 2) * 8 + c) << 15), tid);

            // stage 1: m32 x n64 in TWO n32 passes (pipelined)
            const __half* b1h = (const __half*)(smem + OFF_B1H) + c * 128;
#pragma unroll
            for (int nh = 0; nh < 2; nh++){
                int n0 = nhalf * 64 + nh * 32;
                float acc1[2][4][4];
#pragma unroll
                for (int mt = 0; mt < 2; mt++)
#pragma unroll
                    for (int nt = 0; nt < 4; nt++)
#pragma unroll
                        for (int i = 0; i < 4; i++) acc1[mt][nt][i] = 0.f;

                gemm1_pass(acc1, sX, sWA, m1, n0, lrow, lkhi, axor);

                // epilogue for this n32 half: gelu -> act tile [128,128] RS256
#pragma unroll
                for (int mt = 0; mt < 2; mt++)
#pragma unroll
                for (int nt = 0; nt < 4; nt++){
                    float* d = acc1[mt][nt];
                    int r0 = m1 + mt * 16 + (lane >> 2);
                    int ncol = n0 + nt * 8 + (lane & 3) * 2;
                    half2 bh = *(const half2*)(b1h + ncol);
                    float bb0 = __half2float(__low2half(bh));
                    float bb1 = __half2float(__high2half(bh));
                    uint32_t cb = ((uint32_t)ncol * 2) ^ xr;
#pragma unroll
                    for (int h = 0; h < 2; h++){
                        float g0 = gelu_tanh(d[h * 2]     + bb0);
                        float g1 = gelu_tanh(d[h * 2 + 1] + bb1);
                        *(half2*)(smem + OFF_ACT + (uint32_t)(r0 + h * 8) * 256 + cb)
                            = __floats2half2_rn(g0, g1);
                    }
                }
            }
            cp_wait0(); __syncthreads();               // W2(c) ready; acts visible; WA free
            if (c < 7) pf_tile<65536>(sWA, g_B1 + ((size_t)(e * 8 + c + 1) << 15), tid);
            gemm2_pass<8, 256>(acc2, sACT, sWB, m2, o2, lrow, lkhi, axor);
        }
    } else {
        // =========================== KAN path (chunks of 64 H) ============================
        const uint32_t sWA = sb + OFF_KWA, sWB = sb + OFF_KWB, sKT = sb + OFF_KT;
        int n1 = nhalf * 32;
        for (int cc = 0; cc < 16; cc++){
            int c = cc >> 1, hh = cc & 1;
            const __half* poly = g_B2k + ((size_t)((e * 8 + c) * 3) << 15);

            cp_wait0(); __syncthreads();               // W1k(cc) ready; WB free
            pf_poly_half(sWB, poly, hh, tid);          // P1

            // stage 1: m32 x n32, K=256 (pipelined)
            float acc1[2][4][4];
#pragma unroll
            for (int mt = 0; mt < 2; mt++)
#pragma unroll
                for (int nt = 0; nt < 4; nt++)
#pragma unroll
                    for (int i = 0; i < 4; i++) acc1[mt][nt][i] = 0.f;

            gemm1_pass(acc1, sX, sWA, m1, n1, lrow, lkhi, axor);

            // epilogue 1: t, T2, T3 -> 3 tiles [128,64] RS128
#pragma unroll
            for (int mt = 0; mt < 2; mt++)
#pragma unroll
            for (int nt = 0; nt < 4; nt++){
                float* d = acc1[mt][nt];
                int r0 = m1 + mt * 16 + (lane >> 2);
                int ncol = n1 + nt * 8 + (lane & 3) * 2;
                uint32_t cb = ((uint32_t)ncol * 2) ^ xr;
#pragma unroll
                for (int h = 0; h < 2; h++){
                    float t0 = tanh_fast(d[h * 2]);
                    float t1 = tanh_fast(d[h * 2 + 1]);
                    float u0 = fmaf(2.f * t0, t0, -1.f);
                    float u1 = fmaf(2.f * t1, t1, -1.f);
                    float w0 = fmaf(2.f * t0, u0, -t0);
                    float w1 = fmaf(2.f * t1, u1, -t1);
                    uint32_t ro = (uint32_t)(r0 + h * 8) * 128 + cb;
                    *(half2*)(smem + OFF_KT         + ro) = __floats2half2_rn(t0, t1);
                    *(half2*)(smem + OFF_KT + 16384 + ro) = __floats2half2_rn(u0, u1);
                    *(half2*)(smem + OFF_KT + 32768 + ro) = __floats2half2_rn(w0, w1);
                }
            }
            cp_wait0(); __syncthreads();               // P1 ready; acts visible; WA free
            pf_poly_half(sWA, poly + TILE_HALFS, hh, tid);          // P2
            gemm2_pass<4, 128>(acc2, sKT, sWB, m2, o2, lrow, lkhi, axor);

            cp_wait0(); __syncthreads();               // P2 ready; WB free
            pf_poly_half(sWB, poly + 2 * TILE_HALFS, hh, tid);      // P3
            gemm2_pass<4, 128>(acc2, sKT + 16384, sWA, m2, o2, lrow, lkhi, axor);

            cp_wait0(); __syncthreads();               // P3 ready; WA free
            if (cc < 15){
                int nc = cc + 1;
                pf_tile<32768>(sWA, g_B1 + (((size_t)(e * 8 + (nc >> 1)) << 15)
                                            + ((size_t)(nc & 1) << 14)), tid);
            }
            gemm2_pass<4, 128>(acc2, sKT + 32768, sWB, m2, o2, lrow, lkhi, axor);
        }
    }

    // ---------- final store: acc2 + bias -> gmem fp32 ----------
    float bb[8][2];
#pragma unroll
    for (int blk = 0; blk < 8; blk++){
        int oc = o2 + blk * 8 + (lane & 3) * 2;
        if (is_kan){
            bb[blk][0] = __ldg(kan_bias + e * 256 + oc)     + g_c0[e * 256 + oc];
            bb[blk][1] = __ldg(kan_bias + e * 256 + oc + 1) + g_c0[e * 256 + oc + 1];
        } else {
            bb[blk][0] = __ldg(mlp_b2 + (e - 2) * 256 + oc);
            bb[blk][1] = __ldg(mlp_b2 + (e - 2) * 256 + oc + 1);
        }
    }
#pragma unroll
    for (int mt = 0; mt < 4; mt++)
#pragma unroll
    for (int blk = 0; blk < 8; blk++){
        float* d = acc2[mt][blk];
        int r0 = row0 + m2 + mt * 16 + (lane >> 2);
        int oc = o2 + blk * 8 + (lane & 3) * 2;
        float* op0 = out + (size_t)r0 * 2048 + e * 256 + oc;
        float* op1 = op0 + 8 * 2048;
        op0[0] = d[0] + bb[blk][0];  op0[1] = d[1] + bb[blk][1];
        op1[0] = d[2] + bb[blk][0];  op1[1] = d[3] + bb[blk][1];
    }
}

// ---------------- kernel_launch ----------------
extern "C" void kernel_launch(void* const* d_in, const int* in_sizes, int n_in,
                              void* d_out, int out_size)
{
    const float* x   = (const float*)d_in[0];
    const float* klw = (const float*)d_in[1];
    const float* kpw = (const float*)d_in[2];
    const float* kb  = (const float*)d_in[3];
    const float* w1  = (const float*)d_in[4];
    const float* b1  = (const float*)d_in[5];
    const float* w2  = (const float*)d_in[6];
    const float* b2  = (const float*)d_in[7];
    float* out = (float*)d_out;
    (void)in_sizes; (void)n_in; (void)out_size;

    cudaFuncSetAttribute(prep_tiles, cudaFuncAttributeMaxDynamicSharedMemorySize, 65536);
    cudaFuncSetAttribute(ffn_main,   cudaFuncAttributeMaxDynamicSharedMemorySize, SMEM_MAIN);

    prep_tiles<<<162, 256, 65536>>>(klw, w1, w2, kpw);
    ffn_main<<<1024, NTHREADS, SMEM_MAIN>>>(x, kb, b1, b2, out);
}

// round 13
// speedup vs baseline: 2.3880x; 1.0137x over previous
#include <cuda_runtime.h>
#include <cuda_fp16.h>
#include <cstdint>

// GroupedHybridFFN: B=4,S=4096,D=2048; E=8 experts of d=256; H=1024
//   e 0..1: KAN (lin -> tanh -> Chebyshev T1..T3 -> poly proj; T0 folded to bias)
//   e 2..7: MLP (w1 -> gelu(tanh) -> w2)
// R13: R9 base (best: 684us) + exact-sigmoid gelu (v/(1+e^{-2i})), cutting the
//      MLP epilogue instruction count ~30% to free issue slots for HMMA.

#define TILE_HALFS 32768          // 64KB fp16 weight tile

// smem layout (bytes) — MLP view
#define OFF_B1H   0               // 1024 halfs (mlp b1, whole expert)
#define OFF_X     2048            // 64KB  X tile [128,256] swizzled (512B rows)
#define OFF_WA    67584           // 64KB  weight buffer A (W1 chunk)
#define OFF_WB    133120          // 64KB  weight buffer B (W2 chunk)
#define OFF_ACT   198656          // 32KB  act tile [128,128] (256B rows)
// KAN view (same block): KWA/KWB 32KB each, 3 act tiles 16KB each
#define OFF_KWA   67584
#define OFF_KWB   100352
#define OFF_KT    133120          // 3 x 16KB [128,64] (128B rows)
#define SMEM_MAIN 231424

#define NTHREADS  256

static __device__ __align__(128) __half g_B1 [64u * TILE_HALFS];  // [e8][c8]  N128,K256 RS512
static __device__ __align__(128) __half g_B2m[48u * TILE_HALFS];  // [e6][c8]  N256,K128 RS256
static __device__ __align__(128) __half g_B2k[48u * TILE_HALFS];  // [(e*8+c)*3+p] N256,K128 RS256
static __device__ float g_c0[512];

// ---------------- helpers ----------------
__device__ __forceinline__ uint32_t smem_u32(const void* p){
    uint32_t a;
    asm("{ .reg .u64 t; cvta.to.shared.u64 t, %1; cvt.u32.u64 %0, t; }" : "=r"(a) : "l"(p));
    return a;
}
__device__ __forceinline__ void cpa16(uint32_t dst, const void* src){
    asm volatile("cp.async.cg.shared.global [%0], [%1], 16;" :: "r"(dst), "l"(src) : "memory");
}
__device__ __forceinline__ void cp_commit(){ asm volatile("cp.async.commit_group;" ::: "memory"); }
__device__ __forceinline__ void cp_wait0(){ asm volatile("cp.async.wait_group 0;" ::: "memory"); }

__device__ __forceinline__ void ldmx4(uint32_t (&r)[4], uint32_t addr){
    asm volatile("ldmatrix.sync.aligned.m8n8.x4.shared.b16 {%0,%1,%2,%3}, [%4];"
        : "=r"(r[0]), "=r"(r[1]), "=r"(r[2]), "=r"(r[3]) : "r"(addr));
}
__device__ __forceinline__ void mma16816(float (&d)[4], const uint32_t (&a)[4],
                                         uint32_t b0, uint32_t b1){
    asm volatile("mma.sync.aligned.m16n8k16.row.col.f32.f16.f16.f32 "
        "{%0,%1,%2,%3},{%4,%5,%6,%7},{%8,%9},{%0,%1,%2,%3};"
        : "+f"(d[0]), "+f"(d[1]), "+f"(d[2]), "+f"(d[3])
        : "r"(a[0]), "r"(a[1]), "r"(a[2]), "r"(a[3]), "r"(b0), "r"(b1));
}
__device__ __forceinline__ float tanh_fast(float y){
    float e = __expf(2.0f * y);
    return 1.0f - __fdividef(2.0f, e + 1.0f);
}
// EXACT rewrite of 0.5*v*(1+tanh(0.79788456*(v + 0.044715 v^3))):
//   = v / (1 + exp(-2*0.79788456 * v * (1 + 0.044715 v^2)))
__device__ __forceinline__ float gelu_fast(float v){
    float v2 = v * v;
    float t  = fmaf(0.044715f, v2, 1.0f);
    float E  = (v * -1.5957691216057308f) * t;
    return __fdividef(v, 1.0f + __expf(E));
}
// contiguous NB-byte stream into smem + commit (256 threads)
template<int NB>
__device__ __forceinline__ void pf_tile(uint32_t sdst, const __half* src, int tid){
#pragma unroll
    for (int i = 0; i < NB / (NTHREADS * 16); i++)
        cpa16(sdst + (uint32_t)(i * NTHREADS + tid) * 16, src + (size_t)(i * NTHREADS + tid) * 8);
    cp_commit();
}
// KAN poly k-half sub-tile: src [256,128] RS256 -> dst [256,64] RS128 (half h)
__device__ __forceinline__ void pf_poly_half(uint32_t sdst, const __half* src, int h, int tid){
#pragma unroll
    for (int i = 0; i < 8; i++){
        int idx = i * NTHREADS + tid;            // 2048 granules of 16B
        uint32_t n = (uint32_t)idx >> 3, g = ((uint32_t)idx & 7u) * 16;
        cpa16(sdst + n * 128 + g, src + (size_t)n * 128 + (size_t)h * 64 + g / 2);
    }
    cp_commit();
}

// ---------------- prep: fp32 weights -> fp16 swizzled [N,K] tiles (+ c0 sums) ------
// layout: byte_off(n,k) = n*(2K) + ((2k) ^ ((n&7)<<4))
__global__ void __launch_bounds__(256) prep_tiles(
    const float* __restrict__ kan_lin_w, const float* __restrict__ mlp_w1,
    const float* __restrict__ mlp_w2,    const float* __restrict__ kan_poly_w)
{
    extern __shared__ __half sh[];
    int bid = blockIdx.x, tid = threadIdx.x;

    if (bid >= 160){                        // c0: colsum of kan poly W0 (experts 0,1)
        int e = bid - 160;
        const float* p0 = kan_poly_w + (size_t)e * 4 * 1024 * 256;
        float s = 0.f;
        for (int h = 0; h < 1024; h++) s += p0[(size_t)h * 256 + tid];
        g_c0[e * 256 + tid] = s;
        return;
    }

    const float* src; __half* dst;
    uint32_t N, RS, sstr;

    if (bid < 64){                         // B1: B[n,k] = W1[k][c*128+n]
        int e = bid >> 3, c = bid & 7;
        src = (e < 2 ? kan_lin_w + (size_t)e * 256 * 1024
                     : mlp_w1   + (size_t)(e - 2) * 256 * 1024) + c * 128;
        N = 128; RS = 512; sstr = 1024; dst = g_B1 + (size_t)bid * TILE_HALFS;
    } else if (bid < 112){                 // B2m: B[n,k] = W2[c*128+k][n]
        int i = bid - 64; int e = i >> 3, c = i & 7;
        src = mlp_w2 + (size_t)e * 1024 * 256 + (size_t)c * 128 * 256;
        N = 256; RS = 256; sstr = 256; dst = g_B2m + (size_t)i * TILE_HALFS;
    } else {                               // B2k: poly p=1..3
        int i = bid - 112; int e = i / 24; int r = i % 24; int c = r / 3; int p = r % 3;
        src = kan_poly_w + (size_t)e * 4 * 1024 * 256 + (size_t)(p + 1) * 1024 * 256
            + (size_t)c * 128 * 256;
        N = 256; RS = 256; sstr = 256; dst = g_B2k + (size_t)i * TILE_HALFS;
    }
    for (uint32_t idx = tid; idx < TILE_HALFS; idx += 256){
        uint32_t n = idx & (N - 1), k = idx / N;
        uint32_t off = n * RS + ((k * 2) ^ ((n & 7u) << 4));
        sh[off >> 1] = __float2half_rn(src[(size_t)k * sstr + n]);
    }
    __syncthreads();
    const uint4* s4 = (const uint4*)sh;
    uint4* d4 = (uint4*)dst;
    for (uint32_t t = tid; t < TILE_HALFS / 8; t += 256) d4[t] = s4[t];
}

// ---------------- stage-2 GEMM: acc2 += A[128,KS*16] @ B[256,KS*16]^T --------------
// 8-warp grid 2m x 4o -> warp tile m64 x o64. RS = row stride bytes of both tiles.
template<int KS, int RS>
__device__ __forceinline__ void gemm2_pass(
    float (&acc2)[4][8][4], uint32_t sA, uint32_t sB,
    int m2, int o2, uint32_t lrow, uint32_t lkhi, uint32_t axor)
{
#pragma unroll
    for (int ks = 0; ks < KS; ks++){
        uint32_t kx = ((uint32_t)ks * 32 + lkhi) ^ axor;
        uint32_t a[4][4], b[4][4];
#pragma unroll
        for (int mt = 0; mt < 4; mt++)
            ldmx4(a[mt], sA + (uint32_t)(m2 + mt * 16 + lrow) * RS + kx);
#pragma unroll
        for (int ot = 0; ot < 4; ot++)
            ldmx4(b[ot], sB + (uint32_t)(o2 + ot * 16 + lrow) * RS + kx);
#pragma unroll
        for (int mt = 0; mt < 4; mt++)
#pragma unroll
            for (int ot = 0; ot < 4; ot++){
                mma16816(acc2[mt][ot * 2],     a[mt], b[ot][0], b[ot][2]);
                mma16816(acc2[mt][ot * 2 + 1], a[mt], b[ot][1], b[ot][3]);
            }
    }
}

// ---------------- main fused kernel: 1024 CTAs, 256 threads (8 warps) --------------
__global__ void __launch_bounds__(NTHREADS, 1) ffn_main(
    const float* __restrict__ x,      const float* __restrict__ kan_bias,
    const float* __restrict__ mlp_b1, const float* __restrict__ mlp_b2,
    float* __restrict__ out)
{
    extern __shared__ char smem[];
    uint32_t sb = smem_u32(smem);
    const uint32_t sX = sb + OFF_X;

    int tid = threadIdx.x, wid = tid >> 5, lane = tid & 31;
    int bx = blockIdx.x;
    int e = bx >> 7, tile = bx & 127;          // KAN experts (e<2) first
    int row0 = tile * 128;
    bool is_kan = (e < 2);

    // stage1 grid: 4m x 2n -> warp tile m32 x n{64 mlp | 32 kan}
    int m1 = (wid >> 1) * 32, nhalf = wid & 1;
    // stage2 grid: 2m x 4o -> warp tile m64 x o64
    int m2 = (wid >> 2) * 64, o2 = (wid & 3) * 64;

    uint32_t lrow = lane & 15;
    uint32_t lkhi = (uint32_t)(lane >> 4) << 4;
    uint32_t axor = (lrow & 7u) << 4;
    uint32_t xr = ((uint32_t)(lane >> 2) & 7u) << 4;

    // ---- first weight prefetch (overlaps X load) ----
    if (is_kan) pf_tile<32768>(sb + OFF_KWA, g_B1 + ((size_t)(e * 8) << 15), tid);
    else        pf_tile<65536>(sb + OFF_WA,  g_B1 + ((size_t)(e * 8) << 15), tid);

    // ---- X tile [128,256] fp32 -> fp16 swizzled (512B rows) ----
    const float* xp = x + (size_t)row0 * 2048 + e * 256;
#pragma unroll
    for (int it = 0; it < 32; it++){
        int idx = it * NTHREADS + tid;
        int r = idx >> 6, q = idx & 63;
        float4 v = *(const float4*)(xp + (size_t)r * 2048 + q * 4);
        uint32_t off = (uint32_t)r * 512 + (((uint32_t)q * 8) ^ ((r & 7u) << 4));
        half2 h0 = __floats2half2_rn(v.x, v.y);
        half2 h1 = __floats2half2_rn(v.z, v.w);
        *(uint2*)(smem + OFF_X + off) = make_uint2(*(uint32_t*)&h0, *(uint32_t*)&h1);
    }
    if (!is_kan){
        const float* b1p = mlp_b1 + (size_t)(e - 2) * 1024;
        for (int i = tid; i < 1024; i += NTHREADS)
            ((__half*)(smem + OFF_B1H))[i] = __float2half_rn(b1p[i]);
    }

    // ---- output accumulators: m64 x o64 per warp (128 regs) ----
    float acc2[4][8][4];
#pragma unroll
    for (int mt = 0; mt < 4; mt++)
#pragma unroll
        for (int ot = 0; ot < 8; ot++)
#pragma unroll
            for (int i = 0; i < 4; i++) acc2[mt][ot][i] = 0.f;

    if (!is_kan){
        // =========================== MLP path (chunks of 128 H) ===========================
        const uint32_t sWA = sb + OFF_WA, sWB = sb + OFF_WB, sACT = sb + OFF_ACT;
        int n1 = nhalf * 64;
        for (int c = 0; c < 8; c++){
            cp_wait0(); __syncthreads();               // W1(c) ready; WB free
            pf_tile<65536>(sWB, g_B2m + ((size_t)((e - 2) * 8 + c) << 15), tid);

            // stage 1: m32 x n64, K=256
            float acc1[2][8][4];
#pragma unroll
            for (int mt = 0; mt < 2; mt++)
#pragma unroll
                for (int nt = 0; nt < 8; nt++)
#pragma unroll
                    for (int i = 0; i < 4; i++) acc1[mt][nt][i] = 0.f;
#pragma unroll
            for (int ks = 0; ks < 16; ks++){
                uint32_t kx = ((uint32_t)ks * 32 + lkhi) ^ axor;
                uint32_t a[2][4], b[2][4];
                ldmx4(a[0], sX + (uint32_t)(m1 + lrow) * 512      + kx);
                ldmx4(a[1], sX + (uint32_t)(m1 + 16 + lrow) * 512 + kx);
#pragma unroll
                for (int half = 0; half < 2; half++){
                    ldmx4(b[0], sWA + (uint32_t)(n1 + half * 32 + lrow) * 512      + kx);
                    ldmx4(b[1], sWA + (uint32_t)(n1 + half * 32 + 16 + lrow) * 512 + kx);
#pragma unroll
                    for (int mt = 0; mt < 2; mt++)
#pragma unroll
                        for (int j = 0; j < 2; j++){
                            mma16816(acc1[mt][half * 4 + j * 2],     a[mt], b[j][0], b[j][2]);
                            mma16816(acc1[mt][half * 4 + j * 2 + 1], a[mt], b[j][1], b[j][3]);
                        }
                }
            }
            // epilogue 1: gelu (sigmoid form) -> act tile [128,128] RS256
            {
                const __half* b1h = (const __half*)(smem + OFF_B1H) + c * 128;
#pragma unroll
                for (int mt = 0; mt < 2; mt++)
#pragma unroll
                for (int nt = 0; nt < 8; nt++){
                    float* d = acc1[mt][nt];
                    int r0 = m1 + mt * 16 + (lane >> 2);
                    int ncol = n1 + nt * 8 + (lane & 3) * 2;
                    half2 bh = *(const half2*)(b1h + ncol);
                    float bb0 = __half2float(__low2half(bh));
                    float bb1 = __half2float(__high2half(bh));
                    uint32_t cb = ((uint32_t)ncol * 2) ^ xr;
#pragma unroll
                    for (int h = 0; h < 2; h++){
                        float g0 = gelu_fast(d[h * 2]     + bb0);
                        float g1 = gelu_fast(d[h * 2 + 1] + bb1);
                        *(half2*)(smem + OFF_ACT + (uint32_t)(r0 + h * 8) * 256 + cb)
                            = __floats2half2_rn(g0, g1);
                    }
                }
            }
            cp_wait0(); __syncthreads();               // W2(c) ready; acts visible; WA free
            if (c < 7) pf_tile<65536>(sWA, g_B1 + ((size_t)(e * 8 + c + 1) << 15), tid);
            gemm2_pass<8, 256>(acc2, sACT, sWB, m2, o2, lrow, lkhi, axor);
        }
    } else {
        // =========================== KAN path (chunks of 64 H) ============================
        const uint32_t sWA = sb + OFF_KWA, sWB = sb + OFF_KWB, sKT = sb + OFF_KT;
        int n1 = nhalf * 32;
        for (int cc = 0; cc < 16; cc++){
            int c = cc >> 1, hh = cc & 1;
            const __half* poly = g_B2k + ((size_t)((e * 8 + c) * 3) << 15);

            cp_wait0(); __syncthreads();               // W1k(cc) ready; WB free
            pf_poly_half(sWB, poly, hh, tid);          // P1

            // stage 1: m32 x n32, K=256
            float acc1[2][4][4];
#pragma unroll
            for (int mt = 0; mt < 2; mt++)
#pragma unroll
                for (int nt = 0; nt < 4; nt++)
#pragma unroll
                    for (int i = 0; i < 4; i++) acc1[mt][nt][i] = 0.f;
#pragma unroll
            for (int ks = 0; ks < 16; ks++){
                uint32_t kx = ((uint32_t)ks * 32 + lkhi) ^ axor;
                uint32_t a[2][4], b[2][4];
                ldmx4(a[0], sX  + (uint32_t)(m1 + lrow) * 512      + kx);
                ldmx4(a[1], sX  + (uint32_t)(m1 + 16 + lrow) * 512 + kx);
                ldmx4(b[0], sWA + (uint32_t)(n1 + lrow) * 512      + kx);
                ldmx4(b[1], sWA + (uint32_t)(n1 + 16 + lrow) * 512 + kx);
#pragma unroll
                for (int mt = 0; mt < 2; mt++)
#pragma unroll
                    for (int j = 0; j < 2; j++){
                        mma16816(acc1[mt][j * 2],     a[mt], b[j][0], b[j][2]);
                        mma16816(acc1[mt][j * 2 + 1], a[mt], b[j][1], b[j][3]);
                    }
            }
            // epilogue 1: t, T2, T3 -> 3 tiles [128,64] RS128
#pragma unroll
            for (int mt = 0; mt < 2; mt++)
#pragma unroll
            for (int nt = 0; nt < 4; nt++){
                float* d = acc1[mt][nt];
                int r0 = m1 + mt * 16 + (lane >> 2);
                int ncol = n1 + nt * 8 + (lane & 3) * 2;
                uint32_t cb = ((uint32_t)ncol * 2) ^ xr;
#pragma unroll
                for (int h = 0; h < 2; h++){
                    float t0 = tanh_fast(d[h * 2]);
                    float t1 = tanh_fast(d[h * 2 + 1]);
                    float u0 = fmaf(2.f * t0, t0, -1.f);
                    float u1 = fmaf(2.f * t1, t1, -1.f);
                    float w0 = fmaf(2.f * t0, u0, -t0);
                    float w1 = fmaf(2.f * t1, u1, -t1);
                    uint32_t ro = (uint32_t)(r0 + h * 8) * 128 + cb;
                    *(half2*)(smem + OFF_KT         + ro) = __floats2half2_rn(t0, t1);
                    *(half2*)(smem + OFF_KT + 16384 + ro) = __floats2half2_rn(u0, u1);
                    *(half2*)(smem + OFF_KT + 32768 + ro) = __floats2half2_rn(w0, w1);
                }
            }
            cp_wait0(); __syncthreads();               // P1 ready; acts visible; WA free
            pf_poly_half(sWA, poly + TILE_HALFS, hh, tid);          // P2
            gemm2_pass<4, 128>(acc2, sKT, sWB, m2, o2, lrow, lkhi, axor);

            cp_wait0(); __syncthreads();               // P2 ready; WB free
            pf_poly_half(sWB, poly + 2 * TILE_HALFS, hh, tid);      // P3
            gemm2_pass<4, 128>(acc2, sKT + 16384, sWA, m2, o2, lrow, lkhi, axor);

            cp_wait0(); __syncthreads();               // P3 ready; WA free
            if (cc < 15){
                int nc = cc + 1;
                pf_tile<32768>(sWA, g_B1 + (((size_t)(e * 8 + (nc >> 1)) << 15)
                                            + ((size_t)(nc & 1) << 14)), tid);
            }
            gemm2_pass<4, 128>(acc2, sKT + 32768, sWB, m2, o2, lrow, lkhi, axor);
        }
    }

    // ---------- final store: acc2 + bias -> gmem fp32 ----------
    float bb[8][2];
#pragma unroll
    for (int blk = 0; blk < 8; blk++){
        int oc = o2 + blk * 8 + (lane & 3) * 2;
        if (is_kan){
            bb[blk][0] = __ldg(kan_bias + e * 256 + oc)     + g_c0[e * 256 + oc];
            bb[blk][1] = __ldg(kan_bias + e * 256 + oc + 1) + g_c0[e * 256 + oc + 1];
        } else {
            bb[blk][0] = __ldg(mlp_b2 + (e - 2) * 256 + oc);
            bb[blk][1] = __ldg(mlp_b2 + (e - 2) * 256 + oc + 1);
        }
    }
#pragma unroll
    for (int mt = 0; mt < 4; mt++)
#pragma unroll
    for (int blk = 0; blk < 8; blk++){
        float* d = acc2[mt][blk];
        int r0 = row0 + m2 + mt * 16 + (lane >> 2);
        int oc = o2 + blk * 8 + (lane & 3) * 2;
        float* op0 = out + (size_t)r0 * 2048 + e * 256 + oc;
        float* op1 = op0 + 8 * 2048;
        op0[0] = d[0] + bb[blk][0];  op0[1] = d[1] + bb[blk][1];
        op1[0] = d[2] + bb[blk][0];  op1[1] = d[3] + bb[blk][1];
    }
}

// ---------------- kernel_launch ----------------
extern "C" void kernel_launch(void* const* d_in, const int* in_sizes, int n_in,
                              void* d_out, int out_size)
{
    const float* x   = (const float*)d_in[0];
    const float* klw = (const float*)d_in[1];
    const float* kpw = (const float*)d_in[2];
    const float* kb  = (const float*)d_in[3];
    const float* w1  = (const float*)d_in[4];
    const float* b1  = (const float*)d_in[5];
    const float* w2  = (const float*)d_in[6];
    const float* b2  = (const float*)d_in[7];
    float* out = (float*)d_out;
    (void)in_sizes; (void)n_in; (void)out_size;

    cudaFuncSetAttribute(prep_tiles, cudaFuncAttributeMaxDynamicSharedMemorySize, 65536);
    cudaFuncSetAttribute(ffn_main,   cudaFuncAttributeMaxDynamicSharedMemorySize, SMEM_MAIN);

    prep_tiles<<<162, 256, 65536>>>(klw, w1, w2, kpw);
    ffn_main<<<1024, NTHREADS, SMEM_MAIN>>>(x, kb, b1, b2, out);
}